// round 13
// baseline (speedup 1.0000x reference)
#include <cuda_runtime.h>
#include <cuda_fp16.h>

#define Wd 256
#define Hd 256
#define Bd 64
#define NPIX (Bd*Hd*Wd)
#define NV   (NPIX/4)
#define EPSf 1e-12f

// ---- iteration-invariant scratch (fp32) ----
__device__ __align__(16) float g_g2x[NPIX];
__device__ __align__(16) float g_g2y[NPIX];
__device__ __align__(16) float g_rc [NPIX];
// ---- dual state, fp16 packed per pixel: pa = (p11,p21), pb = (p12,p22) ----
__device__ __align__(16) unsigned g_pa[NPIX];
__device__ __align__(16) unsigned g_pb[NPIX];

union F4 { float4 v; float f[4]; };

__device__ __forceinline__ float4 ld4(const float* p) { return *reinterpret_cast<const float4*>(p); }
__device__ __forceinline__ void   st4(float* p, float4 v) { *reinterpret_cast<float4*>(p) = v; }
__device__ __forceinline__ uint4  ldu4(const unsigned* p) { return *reinterpret_cast<const uint4*>(p); }
__device__ __forceinline__ void   stu4(unsigned* p, uint4 v) { *reinterpret_cast<uint4*>(p) = v; }

// decode one packed word -> (lo, hi) floats
__device__ __forceinline__ float2 h2f(unsigned w) {
    __half2 h = *reinterpret_cast<__half2*>(&w);
    return __half22float2(h);
}
// encode two floats -> packed word (RN)
__device__ __forceinline__ unsigned f2h(float a, float b) {
    __half2 h = __floats2half2_rn(a, b);
    return *reinterpret_cast<unsigned*>(&h);
}
__device__ __forceinline__ unsigned u4get(const uint4& u, int k) {
    return (k == 0) ? u.x : (k == 1) ? u.y : (k == 2) ? u.z : u.w;
}
__device__ __forceinline__ void u4set(uint4& u, int k, unsigned v) {
    if (k == 0) u.x = v; else if (k == 1) u.y = v; else if (k == 2) u.z = v; else u.w = v;
}

// ============================================================================
// Init: g2x, g2y (centered grads of y, x boundary), rc = y-x, iter-1 u.
// ============================================================================
__global__ void __launch_bounds__(256) k_init(
    const float* __restrict__ x, const float* __restrict__ y,
    const float* __restrict__ tp, const float* __restrict__ lp,
    float* __restrict__ u1, float* __restrict__ u2)
{
    int v = blockIdx.x * blockDim.x + threadIdx.x;
    if (v >= NV) return;
    int idx = v << 2;
    int j4 = idx & (Wd - 1);
    int i  = (idx >> 8) & (Hd - 1);

    float ts  = tp[0];
    float l_t = lp[0] * ts;

    F4 X, Y, Yu, Yd, Xu, Xd;
    X.v = ld4(x + idx);
    Y.v = ld4(y + idx);
    float yl = (j4 > 0)       ? y[idx - 1] : 0.f;
    float yr = (j4 + 4 < Wd)  ? y[idx + 4] : 0.f;
    Yu.v = (i > 0)      ? ld4(y + idx - Wd) : make_float4(0,0,0,0);
    Yd.v = (i < Hd - 1) ? ld4(y + idx + Wd) : make_float4(0,0,0,0);
    Xd.v = (i == 0)      ? ld4(x + idx + Wd) : make_float4(0,0,0,0);
    Xu.v = (i == Hd - 1) ? ld4(x + idx - Wd) : make_float4(0,0,0,0);

    F4 GX, GY, RC, O1, O2;
#pragma unroll
    for (int k = 0; k < 4; k++) {
        int j = j4 + k;
        float gx;
        if (j == 0)            gx = 0.5f * (X.f[1] - X.f[0]);
        else if (j == Wd - 1)  gx = 0.5f * (X.f[3] - X.f[2]);
        else {
            float yn = (k < 3) ? Y.f[k + 1] : yr;
            float yp = (k > 0) ? Y.f[k - 1] : yl;
            gx = 0.5f * (yn - yp);
        }
        float gy;
        if (i == 0)            gy = 0.5f * (Xd.f[k] - X.f[k]);
        else if (i == Hd - 1)  gy = 0.5f * (X.f[k] - Xu.f[k]);
        else                   gy = 0.5f * (Yd.f[k] - Yu.f[k]);

        float rc = Y.f[k] - X.f[k];
        GX.f[k] = gx; GY.f[k] = gy; RC.f[k] = rc;

        float rho  = rc + EPSf;
        float grad = gx * gx + gy * gy + EPSf;
        float lg   = l_t * grad;
        float v1, v2;
        if      (rho < -lg)   { v1 =  l_t * gx; v2 =  l_t * gy; }
        else if (rho >  lg)   { v1 = -l_t * gx; v2 = -l_t * gy; }
        else if (grad > EPSf) { float s = -rho / grad; v1 = s * gx; v2 = s * gy; }
        else                  { v1 = 0.f; v2 = 0.f; }
        O1.f[k] = v1; O2.f[k] = v2;
    }
    st4(g_g2x + idx, GX.v);
    st4(g_g2y + idx, GY.v);
    st4(g_rc  + idx, RC.v);
    st4(u1 + idx, O1.v);
    st4(u2 + idx, O2.v);
}

// ============================================================================
// P update: forward grads of u, dual projection. In-place packed fp16 p.
// ============================================================================
template <bool FIRST>
__global__ void __launch_bounds__(256) k_update_p(
    const float* __restrict__ tp, const float* __restrict__ ap,
    const float* __restrict__ u1, const float* __restrict__ u2)
{
    int v = blockIdx.x * blockDim.x + threadIdx.x;
    if (v >= NV) return;
    int idx = v << 2;
    int j4 = idx & (Wd - 1);
    int i  = (idx >> 8) & (Hd - 1);

    float taut = ap[0] / tp[0];

    F4 U1, U2, U1d, U2d;
    U1.v = ld4(u1 + idx);
    U2.v = ld4(u2 + idx);
    float u1r = (j4 + 4 < Wd) ? u1[idx + 4] : 0.f;
    float u2r = (j4 + 4 < Wd) ? u2[idx + 4] : 0.f;
    bool has_down = (i < Hd - 1);
    U1d.v = has_down ? ld4(u1 + idx + Wd) : make_float4(0,0,0,0);
    U2d.v = has_down ? ld4(u2 + idx + Wd) : make_float4(0,0,0,0);

    uint4 PA = make_uint4(0,0,0,0), PB = make_uint4(0,0,0,0);
    if (!FIRST) {
        PA = ldu4(g_pa + idx);
        PB = ldu4(g_pb + idx);
    }

    uint4 OA, OB;
#pragma unroll
    for (int k = 0; k < 4; k++) {
        int j = j4 + k;
        float u1x = (j < Wd - 1) ? ((k < 3) ? U1.f[k + 1] : u1r) - U1.f[k] : 0.f;
        float u2x = (j < Wd - 1) ? ((k < 3) ? U2.f[k + 1] : u2r) - U2.f[k] : 0.f;
        float u1y = has_down ? (U1d.f[k] - U1.f[k]) : 0.f;
        float u2y = has_down ? (U2d.f[k] - U2.f[k]) : 0.f;

        float n1 = sqrtf(u1x * u1x + u1y * u1y + EPSf);
        float n2 = sqrtf(u2x * u2x + u2y * u2y + EPSf);
        float f1 = 1.0f / (1.0f + taut * n1);
        float f2 = 1.0f / (1.0f + taut * n2);

        float p11o = 0.f, p21o = 0.f, p12o = 0.f, p22o = 0.f;
        if (!FIRST) {
            float2 a = h2f(u4get(PA, k));
            float2 b = h2f(u4get(PB, k));
            p11o = a.x; p21o = a.y; p12o = b.x; p22o = b.y;
        }

        float o11 = (p11o + taut * u1x) * f1;
        float o12 = (p12o + taut * u1y) * f1;
        float o21 = (p21o + taut * u2x) * f2;
        float o22 = (p22o + taut * u2y) * f2;
        u4set(OA, k, f2h(o11, o21));
        u4set(OB, k, f2h(o12, o22));
    }
    stu4(g_pa + idx, OA);
    stu4(g_pb + idx, OB);
}

// ============================================================================
// U update: thresholding + u = v + ts * div(p). In-place u.
// ============================================================================
__global__ void __launch_bounds__(256) k_update_u(
    const float* __restrict__ tp, const float* __restrict__ lp,
    float* __restrict__ u1, float* __restrict__ u2)
{
    int v = blockIdx.x * blockDim.x + threadIdx.x;
    if (v >= NV) return;
    int idx = v << 2;
    int j4 = idx & (Wd - 1);
    int i  = (idx >> 8) & (Hd - 1);

    float ts  = tp[0];
    float l_t = lp[0] * ts;

    F4 U1, U2, GX, GY, RC;
    U1.v  = ld4(u1 + idx);
    U2.v  = ld4(u2 + idx);
    GX.v  = ld4(g_g2x + idx);
    GY.v  = ld4(g_g2y + idx);
    RC.v  = ld4(g_rc + idx);
    uint4 PA = ldu4(g_pa + idx);   // (p11,p21) x4
    uint4 PB = ldu4(g_pb + idx);   // (p12,p22) x4
    float p11l = 0.f, p21l = 0.f;
    if (j4 > 0) {
        float2 a = h2f(g_pa[idx - 1]);
        p11l = a.x; p21l = a.y;
    }
    bool has_up = (i > 0);
    uint4 PBu = has_up ? ldu4(g_pb + idx - Wd) : make_uint4(0,0,0,0);

    F4 O1, O2;
#pragma unroll
    for (int k = 0; k < 4; k++) {
        int j = j4 + k;
        float2 a  = h2f(u4get(PA, k));    // p11, p21
        float2 b  = h2f(u4get(PB, k));    // p12, p22
        float2 bu = h2f(u4get(PBu, k));   // p12u, p22u

        float lft11, lft21;
        if (k > 0) {
            float2 al = h2f(u4get(PA, k - 1));
            lft11 = al.x; lft21 = al.y;
        } else { lft11 = p11l; lft21 = p21l; }

        float dx1 = (j == 0) ? a.x : (a.x - lft11);
        float dx2 = (j == 0) ? a.y : (a.y - lft21);
        float dy1 = has_up ? (b.x - bu.x) : b.x;
        float dy2 = has_up ? (b.y - bu.y) : b.y;

        float gx = GX.f[k], gy = GY.f[k];
        float rho  = RC.f[k] + gx * U1.f[k] + gy * U2.f[k] + EPSf;
        float grad = gx * gx + gy * gy + EPSf;
        float lg   = l_t * grad;
        float v1, v2;
        if      (rho < -lg)   { v1 =  l_t * gx; v2 =  l_t * gy; }
        else if (rho >  lg)   { v1 = -l_t * gx; v2 = -l_t * gy; }
        else if (grad > EPSf) { float s = -rho / grad; v1 = s * gx; v2 = s * gy; }
        else                  { v1 = 0.f; v2 = 0.f; }

        O1.f[k] = U1.f[k] + v1 + ts * (dx1 + dy1);
        O2.f[k] = U2.f[k] + v2 + ts * (dx2 + dy2);
    }
    st4(u1 + idx, O1.v);
    st4(u2 + idx, O2.v);
}

// ============================================================================
// Launch: full batch, 19 launches. Working set u 32MB + p 32MB + g 48MB =
// 112MB < 126MB L2 (fp16 p makes full-batch residency possible).
// ============================================================================
extern "C" void kernel_launch(void* const* d_in, const int* in_sizes, int n_in,
                              void* d_out, int out_size)
{
    const float* x = (const float*)d_in[0];
    const float* y = (const float*)d_in[1];
    const float* t = (const float*)d_in[8];
    const float* l = (const float*)d_in[9];
    const float* a = (const float*)d_in[10];

    float* u1 = (float*)d_out;
    float* u2 = u1 + NPIX;

    const int threads = 256;
    const int blocks  = (NV + threads - 1) / threads;

    k_init<<<blocks, threads>>>(x, y, t, l, u1, u2);
    k_update_p<true><<<blocks, threads>>>(t, a, u1, u2);
    for (int it = 0; it < 9; ++it) {
        k_update_u<<<blocks, threads>>>(t, l, u1, u2);
        if (it < 8)
            k_update_p<false><<<blocks, threads>>>(t, a, u1, u2);
    }
}

// round 14
// speedup vs baseline: 1.1200x; 1.1200x over previous
#include <cuda_runtime.h>
#include <cuda_fp16.h>

#define Wd 256
#define Hd 256
#define Bd 64
#define NPIX (Bd*Hd*Wd)
#define HPIX (NPIX/2)      // elements per batch half
#define NVH  (HPIX/4)      // float4 vectors per half
#define EPSf 1e-12f

// ---- iteration-invariant scratch (fp32) ----
__device__ __align__(16) float g_g2x[NPIX];
__device__ __align__(16) float g_g2y[NPIX];
__device__ __align__(16) float g_rc [NPIX];
// ---- dual state, fp16 packed per pixel: pa = (p11,p21), pb = (p12,p22) ----
__device__ __align__(16) unsigned g_pa[NPIX];
__device__ __align__(16) unsigned g_pb[NPIX];

union F4 { float4 v; float f[4]; };

__device__ __forceinline__ float4 ld4(const float* p) { return *reinterpret_cast<const float4*>(p); }
__device__ __forceinline__ void   st4(float* p, float4 v) { *reinterpret_cast<float4*>(p) = v; }
__device__ __forceinline__ uint4  ldu4(const unsigned* p) { return *reinterpret_cast<const uint4*>(p); }
__device__ __forceinline__ void   stu4(unsigned* p, uint4 v) { *reinterpret_cast<uint4*>(p) = v; }

__device__ __forceinline__ float2 h2f(unsigned w) {
    __half2 h = *reinterpret_cast<__half2*>(&w);
    return __half22float2(h);
}
__device__ __forceinline__ unsigned f2h(float a, float b) {
    __half2 h = __floats2half2_rn(a, b);
    return *reinterpret_cast<unsigned*>(&h);
}
__device__ __forceinline__ unsigned u4get(const uint4& u, int k) {
    return (k == 0) ? u.x : (k == 1) ? u.y : (k == 2) ? u.z : u.w;
}
__device__ __forceinline__ void u4set(uint4& u, int k, unsigned v) {
    if (k == 0) u.x = v; else if (k == 1) u.y = v; else if (k == 2) u.z = v; else u.w = v;
}

// ============================================================================
// Init (per half): g2x, g2y (centered grads of y, x boundary), rc, iter-1 u.
// ============================================================================
__global__ void __launch_bounds__(256) k_init(
    const float* __restrict__ x, const float* __restrict__ y,
    const float* __restrict__ tp, const float* __restrict__ lp,
    float* __restrict__ u1, float* __restrict__ u2, int off)
{
    int v = blockIdx.x * blockDim.x + threadIdx.x;
    if (v >= NVH) return;
    int il = v << 2;
    int idx = il + off;
    int j4 = il & (Wd - 1);
    int i  = (il >> 8) & (Hd - 1);

    float ts  = tp[0];
    float l_t = lp[0] * ts;

    F4 X, Y, Yu, Yd, Xu, Xd;
    X.v = ld4(x + idx);
    Y.v = ld4(y + idx);
    float yl = (j4 > 0)       ? y[idx - 1] : 0.f;
    float yr = (j4 + 4 < Wd)  ? y[idx + 4] : 0.f;
    Yu.v = (i > 0)      ? ld4(y + idx - Wd) : make_float4(0,0,0,0);
    Yd.v = (i < Hd - 1) ? ld4(y + idx + Wd) : make_float4(0,0,0,0);
    Xd.v = (i == 0)      ? ld4(x + idx + Wd) : make_float4(0,0,0,0);
    Xu.v = (i == Hd - 1) ? ld4(x + idx - Wd) : make_float4(0,0,0,0);

    F4 GX, GY, RC, O1, O2;
#pragma unroll
    for (int k = 0; k < 4; k++) {
        int j = j4 + k;
        float gx;
        if (j == 0)            gx = 0.5f * (X.f[1] - X.f[0]);
        else if (j == Wd - 1)  gx = 0.5f * (X.f[3] - X.f[2]);
        else {
            float yn = (k < 3) ? Y.f[k + 1] : yr;
            float yp = (k > 0) ? Y.f[k - 1] : yl;
            gx = 0.5f * (yn - yp);
        }
        float gy;
        if (i == 0)            gy = 0.5f * (Xd.f[k] - X.f[k]);
        else if (i == Hd - 1)  gy = 0.5f * (X.f[k] - Xu.f[k]);
        else                   gy = 0.5f * (Yd.f[k] - Yu.f[k]);

        float rc = Y.f[k] - X.f[k];
        GX.f[k] = gx; GY.f[k] = gy; RC.f[k] = rc;

        float rho  = rc + EPSf;
        float grad = gx * gx + gy * gy + EPSf;
        float lg   = l_t * grad;
        float v1, v2;
        if      (rho < -lg)   { v1 =  l_t * gx; v2 =  l_t * gy; }
        else if (rho >  lg)   { v1 = -l_t * gx; v2 = -l_t * gy; }
        else if (grad > EPSf) { float s = -rho / grad; v1 = s * gx; v2 = s * gy; }
        else                  { v1 = 0.f; v2 = 0.f; }
        O1.f[k] = v1; O2.f[k] = v2;
    }
    st4(g_g2x + idx, GX.v);
    st4(g_g2y + idx, GY.v);
    st4(g_rc  + idx, RC.v);
    st4(u1 + idx, O1.v);
    st4(u2 + idx, O2.v);
}

// ============================================================================
// P update (per half): forward grads of u, dual projection. In-place packed p.
// ============================================================================
template <bool FIRST>
__global__ void __launch_bounds__(256) k_update_p(
    const float* __restrict__ tp, const float* __restrict__ ap,
    const float* __restrict__ u1, const float* __restrict__ u2, int off)
{
    int v = blockIdx.x * blockDim.x + threadIdx.x;
    if (v >= NVH) return;
    int il = v << 2;
    int idx = il + off;
    int j4 = il & (Wd - 1);
    int i  = (il >> 8) & (Hd - 1);

    float taut = ap[0] / tp[0];

    F4 U1, U2, U1d, U2d;
    U1.v = ld4(u1 + idx);
    U2.v = ld4(u2 + idx);
    float u1r = (j4 + 4 < Wd) ? u1[idx + 4] : 0.f;
    float u2r = (j4 + 4 < Wd) ? u2[idx + 4] : 0.f;
    bool has_down = (i < Hd - 1);
    U1d.v = has_down ? ld4(u1 + idx + Wd) : make_float4(0,0,0,0);
    U2d.v = has_down ? ld4(u2 + idx + Wd) : make_float4(0,0,0,0);

    uint4 PA = make_uint4(0,0,0,0), PB = make_uint4(0,0,0,0);
    if (!FIRST) {
        PA = ldu4(g_pa + idx);
        PB = ldu4(g_pb + idx);
    }

    uint4 OA, OB;
#pragma unroll
    for (int k = 0; k < 4; k++) {
        int j = j4 + k;
        float u1x = (j < Wd - 1) ? ((k < 3) ? U1.f[k + 1] : u1r) - U1.f[k] : 0.f;
        float u2x = (j < Wd - 1) ? ((k < 3) ? U2.f[k + 1] : u2r) - U2.f[k] : 0.f;
        float u1y = has_down ? (U1d.f[k] - U1.f[k]) : 0.f;
        float u2y = has_down ? (U2d.f[k] - U2.f[k]) : 0.f;

        float n1 = sqrtf(u1x * u1x + u1y * u1y + EPSf);
        float n2 = sqrtf(u2x * u2x + u2y * u2y + EPSf);
        float f1 = 1.0f / (1.0f + taut * n1);
        float f2 = 1.0f / (1.0f + taut * n2);

        float p11o = 0.f, p21o = 0.f, p12o = 0.f, p22o = 0.f;
        if (!FIRST) {
            float2 a = h2f(u4get(PA, k));
            float2 b = h2f(u4get(PB, k));
            p11o = a.x; p21o = a.y; p12o = b.x; p22o = b.y;
        }

        float o11 = (p11o + taut * u1x) * f1;
        float o12 = (p12o + taut * u1y) * f1;
        float o21 = (p21o + taut * u2x) * f2;
        float o22 = (p22o + taut * u2y) * f2;
        u4set(OA, k, f2h(o11, o21));
        u4set(OB, k, f2h(o12, o22));
    }
    stu4(g_pa + idx, OA);
    stu4(g_pb + idx, OB);
}

// ============================================================================
// U update (per half): thresholding + u = v + ts * div(p). In-place u.
// ============================================================================
__global__ void __launch_bounds__(256) k_update_u(
    const float* __restrict__ tp, const float* __restrict__ lp,
    float* __restrict__ u1, float* __restrict__ u2, int off)
{
    int v = blockIdx.x * blockDim.x + threadIdx.x;
    if (v >= NVH) return;
    int il = v << 2;
    int idx = il + off;
    int j4 = il & (Wd - 1);
    int i  = (il >> 8) & (Hd - 1);

    float ts  = tp[0];
    float l_t = lp[0] * ts;

    F4 U1, U2, GX, GY, RC;
    U1.v  = ld4(u1 + idx);
    U2.v  = ld4(u2 + idx);
    GX.v  = ld4(g_g2x + idx);
    GY.v  = ld4(g_g2y + idx);
    RC.v  = ld4(g_rc + idx);
    uint4 PA = ldu4(g_pa + idx);   // (p11,p21) x4
    uint4 PB = ldu4(g_pb + idx);   // (p12,p22) x4
    float p11l = 0.f, p21l = 0.f;
    if (j4 > 0) {
        float2 a = h2f(g_pa[idx - 1]);
        p11l = a.x; p21l = a.y;
    }
    bool has_up = (i > 0);
    uint4 PBu = has_up ? ldu4(g_pb + idx - Wd) : make_uint4(0,0,0,0);

    F4 O1, O2;
#pragma unroll
    for (int k = 0; k < 4; k++) {
        int j = j4 + k;
        float2 a  = h2f(u4get(PA, k));    // p11, p21
        float2 b  = h2f(u4get(PB, k));    // p12, p22
        float2 bu = h2f(u4get(PBu, k));   // p12u, p22u

        float lft11, lft21;
        if (k > 0) {
            float2 al = h2f(u4get(PA, k - 1));
            lft11 = al.x; lft21 = al.y;
        } else { lft11 = p11l; lft21 = p21l; }

        float dx1 = (j == 0) ? a.x : (a.x - lft11);
        float dx2 = (j == 0) ? a.y : (a.y - lft21);
        float dy1 = has_up ? (b.x - bu.x) : b.x;
        float dy2 = has_up ? (b.y - bu.y) : b.y;

        float gx = GX.f[k], gy = GY.f[k];
        float rho  = RC.f[k] + gx * U1.f[k] + gy * U2.f[k] + EPSf;
        float grad = gx * gx + gy * gy + EPSf;
        float lg   = l_t * grad;
        float v1, v2;
        if      (rho < -lg)   { v1 =  l_t * gx; v2 =  l_t * gy; }
        else if (rho >  lg)   { v1 = -l_t * gx; v2 = -l_t * gy; }
        else if (grad > EPSf) { float s = -rho / grad; v1 = s * gx; v2 = s * gy; }
        else                  { v1 = 0.f; v2 = 0.f; }

        O1.f[k] = U1.f[k] + v1 + ts * (dx1 + dy1);
        O2.f[k] = U2.f[k] + v2 + ts * (dx2 + dy2);
    }
    st4(u1 + idx, O1.v);
    st4(u2 + idx, O2.v);
}

// ============================================================================
// Launch: full pipeline on batch half 0, then half 1. Per-half working set
// (u 16MB + p 16MB + g 24MB = 56MB) comfortably L2-resident.
// ============================================================================
extern "C" void kernel_launch(void* const* d_in, const int* in_sizes, int n_in,
                              void* d_out, int out_size)
{
    const float* x = (const float*)d_in[0];
    const float* y = (const float*)d_in[1];
    const float* t = (const float*)d_in[8];
    const float* l = (const float*)d_in[9];
    const float* a = (const float*)d_in[10];

    float* u1 = (float*)d_out;
    float* u2 = u1 + NPIX;

    const int threads = 256;
    const int blocks  = (NVH + threads - 1) / threads;

    for (int h = 0; h < 2; ++h) {
        int off = h * HPIX;
        k_init<<<blocks, threads>>>(x, y, t, l, u1, u2, off);
        k_update_p<true><<<blocks, threads>>>(t, a, u1, u2, off);
        for (int it = 0; it < 9; ++it) {
            k_update_u<<<blocks, threads>>>(t, l, u1, u2, off);
            if (it < 8)
                k_update_p<false><<<blocks, threads>>>(t, a, u1, u2, off);
        }
    }
}

// round 15
// speedup vs baseline: 1.3767x; 1.2292x over previous
#include <cuda_runtime.h>
#include <cuda_fp16.h>

#define Wd 256
#define Hd 256
#define Bd 64
#define NPIX (Bd*Hd*Wd)
#define QIMG 16
#define QPIX (QIMG*Hd*Wd)   // elements per quarter
#define NVQ  (QPIX/4)       // float4 vectors per quarter
#define EPSf 1e-12f

// ---- iteration-invariant scratch (fp32) ----
__device__ __align__(16) float g_g2x[NPIX];
__device__ __align__(16) float g_g2y[NPIX];
__device__ __align__(16) float g_rc [NPIX];
// ---- dual state, fp16 packed per pixel: pa = (p11,p21), pb = (p12,p22) ----
__device__ __align__(16) unsigned g_pa[NPIX];
__device__ __align__(16) unsigned g_pb[NPIX];

union F4 { float4 v; float f[4]; };

__device__ __forceinline__ float4 ld4(const float* p) { return *reinterpret_cast<const float4*>(p); }
__device__ __forceinline__ void   st4(float* p, float4 v) { *reinterpret_cast<float4*>(p) = v; }
__device__ __forceinline__ uint4  ldu4(const unsigned* p) { return *reinterpret_cast<const uint4*>(p); }
__device__ __forceinline__ void   stu4(unsigned* p, uint4 v) { *reinterpret_cast<uint4*>(p) = v; }

__device__ __forceinline__ float2 h2f(unsigned w) {
    __half2 h = *reinterpret_cast<__half2*>(&w);
    return __half22float2(h);
}
__device__ __forceinline__ unsigned f2h(float a, float b) {
    __half2 h = __floats2half2_rn(a, b);
    return *reinterpret_cast<unsigned*>(&h);
}
__device__ __forceinline__ unsigned u4get(const uint4& u, int k) {
    return (k == 0) ? u.x : (k == 1) ? u.y : (k == 2) ? u.z : u.w;
}
__device__ __forceinline__ void u4set(uint4& u, int k, unsigned v) {
    if (k == 0) u.x = v; else if (k == 1) u.y = v; else if (k == 2) u.z = v; else u.w = v;
}

// ============================================================================
// Init (per quarter): g2x, g2y (centered grads of y, x boundary), rc, iter-1 u.
// ============================================================================
__global__ void __launch_bounds__(256) k_init(
    const float* __restrict__ x, const float* __restrict__ y,
    const float* __restrict__ tp, const float* __restrict__ lp,
    float* __restrict__ u1, float* __restrict__ u2, int off)
{
    int v = blockIdx.x * blockDim.x + threadIdx.x;
    if (v >= NVQ) return;
    int il = v << 2;
    int idx = il + off;
    int j4 = il & (Wd - 1);
    int i  = (il >> 8) & (Hd - 1);

    float ts  = tp[0];
    float l_t = lp[0] * ts;

    F4 X, Y, Yu, Yd, Xu, Xd;
    X.v = ld4(x + idx);
    Y.v = ld4(y + idx);
    float yl = (j4 > 0)       ? y[idx - 1] : 0.f;
    float yr = (j4 + 4 < Wd)  ? y[idx + 4] : 0.f;
    Yu.v = (i > 0)      ? ld4(y + idx - Wd) : make_float4(0,0,0,0);
    Yd.v = (i < Hd - 1) ? ld4(y + idx + Wd) : make_float4(0,0,0,0);
    Xd.v = (i == 0)      ? ld4(x + idx + Wd) : make_float4(0,0,0,0);
    Xu.v = (i == Hd - 1) ? ld4(x + idx - Wd) : make_float4(0,0,0,0);

    F4 GX, GY, RC, O1, O2;
#pragma unroll
    for (int k = 0; k < 4; k++) {
        int j = j4 + k;
        float gx;
        if (j == 0)            gx = 0.5f * (X.f[1] - X.f[0]);
        else if (j == Wd - 1)  gx = 0.5f * (X.f[3] - X.f[2]);
        else {
            float yn = (k < 3) ? Y.f[k + 1] : yr;
            float yp = (k > 0) ? Y.f[k - 1] : yl;
            gx = 0.5f * (yn - yp);
        }
        float gy;
        if (i == 0)            gy = 0.5f * (Xd.f[k] - X.f[k]);
        else if (i == Hd - 1)  gy = 0.5f * (X.f[k] - Xu.f[k]);
        else                   gy = 0.5f * (Yd.f[k] - Yu.f[k]);

        float rc = Y.f[k] - X.f[k];
        GX.f[k] = gx; GY.f[k] = gy; RC.f[k] = rc;

        float rho  = rc + EPSf;
        float grad = gx * gx + gy * gy + EPSf;
        float lg   = l_t * grad;
        float v1, v2;
        if      (rho < -lg)   { v1 =  l_t * gx; v2 =  l_t * gy; }
        else if (rho >  lg)   { v1 = -l_t * gx; v2 = -l_t * gy; }
        else if (grad > EPSf) { float s = -rho / grad; v1 = s * gx; v2 = s * gy; }
        else                  { v1 = 0.f; v2 = 0.f; }
        O1.f[k] = v1; O2.f[k] = v2;
    }
    st4(g_g2x + idx, GX.v);
    st4(g_g2y + idx, GY.v);
    st4(g_rc  + idx, RC.v);
    st4(u1 + idx, O1.v);
    st4(u2 + idx, O2.v);
}

// ============================================================================
// P update (per quarter): forward grads of u, dual projection. In-place packed p.
// ============================================================================
template <bool FIRST>
__global__ void __launch_bounds__(256) k_update_p(
    const float* __restrict__ tp, const float* __restrict__ ap,
    const float* __restrict__ u1, const float* __restrict__ u2, int off)
{
    int v = blockIdx.x * blockDim.x + threadIdx.x;
    if (v >= NVQ) return;
    int il = v << 2;
    int idx = il + off;
    int j4 = il & (Wd - 1);
    int i  = (il >> 8) & (Hd - 1);

    float taut = ap[0] / tp[0];

    F4 U1, U2, U1d, U2d;
    U1.v = ld4(u1 + idx);
    U2.v = ld4(u2 + idx);
    float u1r = (j4 + 4 < Wd) ? u1[idx + 4] : 0.f;
    float u2r = (j4 + 4 < Wd) ? u2[idx + 4] : 0.f;
    bool has_down = (i < Hd - 1);
    U1d.v = has_down ? ld4(u1 + idx + Wd) : make_float4(0,0,0,0);
    U2d.v = has_down ? ld4(u2 + idx + Wd) : make_float4(0,0,0,0);

    uint4 PA = make_uint4(0,0,0,0), PB = make_uint4(0,0,0,0);
    if (!FIRST) {
        PA = ldu4(g_pa + idx);
        PB = ldu4(g_pb + idx);
    }

    uint4 OA, OB;
#pragma unroll
    for (int k = 0; k < 4; k++) {
        int j = j4 + k;
        float u1x = (j < Wd - 1) ? ((k < 3) ? U1.f[k + 1] : u1r) - U1.f[k] : 0.f;
        float u2x = (j < Wd - 1) ? ((k < 3) ? U2.f[k + 1] : u2r) - U2.f[k] : 0.f;
        float u1y = has_down ? (U1d.f[k] - U1.f[k]) : 0.f;
        float u2y = has_down ? (U2d.f[k] - U2.f[k]) : 0.f;

        float n1 = sqrtf(u1x * u1x + u1y * u1y + EPSf);
        float n2 = sqrtf(u2x * u2x + u2y * u2y + EPSf);
        float f1 = 1.0f / (1.0f + taut * n1);
        float f2 = 1.0f / (1.0f + taut * n2);

        float p11o = 0.f, p21o = 0.f, p12o = 0.f, p22o = 0.f;
        if (!FIRST) {
            float2 a = h2f(u4get(PA, k));
            float2 b = h2f(u4get(PB, k));
            p11o = a.x; p21o = a.y; p12o = b.x; p22o = b.y;
        }

        float o11 = (p11o + taut * u1x) * f1;
        float o12 = (p12o + taut * u1y) * f1;
        float o21 = (p21o + taut * u2x) * f2;
        float o22 = (p22o + taut * u2y) * f2;
        u4set(OA, k, f2h(o11, o21));
        u4set(OB, k, f2h(o12, o22));
    }
    stu4(g_pa + idx, OA);
    stu4(g_pb + idx, OB);
}

// ============================================================================
// U update (per quarter): thresholding + u = v + ts * div(p). In-place u.
// ============================================================================
__global__ void __launch_bounds__(256) k_update_u(
    const float* __restrict__ tp, const float* __restrict__ lp,
    float* __restrict__ u1, float* __restrict__ u2, int off)
{
    int v = blockIdx.x * blockDim.x + threadIdx.x;
    if (v >= NVQ) return;
    int il = v << 2;
    int idx = il + off;
    int j4 = il & (Wd - 1);
    int i  = (il >> 8) & (Hd - 1);

    float ts  = tp[0];
    float l_t = lp[0] * ts;

    F4 U1, U2, GX, GY, RC;
    U1.v  = ld4(u1 + idx);
    U2.v  = ld4(u2 + idx);
    GX.v  = ld4(g_g2x + idx);
    GY.v  = ld4(g_g2y + idx);
    RC.v  = ld4(g_rc + idx);
    uint4 PA = ldu4(g_pa + idx);   // (p11,p21) x4
    uint4 PB = ldu4(g_pb + idx);   // (p12,p22) x4
    float p11l = 0.f, p21l = 0.f;
    if (j4 > 0) {
        float2 a = h2f(g_pa[idx - 1]);
        p11l = a.x; p21l = a.y;
    }
    bool has_up = (i > 0);
    uint4 PBu = has_up ? ldu4(g_pb + idx - Wd) : make_uint4(0,0,0,0);

    F4 O1, O2;
#pragma unroll
    for (int k = 0; k < 4; k++) {
        int j = j4 + k;
        float2 a  = h2f(u4get(PA, k));    // p11, p21
        float2 b  = h2f(u4get(PB, k));    // p12, p22
        float2 bu = h2f(u4get(PBu, k));   // p12u, p22u

        float lft11, lft21;
        if (k > 0) {
            float2 al = h2f(u4get(PA, k - 1));
            lft11 = al.x; lft21 = al.y;
        } else { lft11 = p11l; lft21 = p21l; }

        float dx1 = (j == 0) ? a.x : (a.x - lft11);
        float dx2 = (j == 0) ? a.y : (a.y - lft21);
        float dy1 = has_up ? (b.x - bu.x) : b.x;
        float dy2 = has_up ? (b.y - bu.y) : b.y;

        float gx = GX.f[k], gy = GY.f[k];
        float rho  = RC.f[k] + gx * U1.f[k] + gy * U2.f[k] + EPSf;
        float grad = gx * gx + gy * gy + EPSf;
        float lg   = l_t * grad;
        float v1, v2;
        if      (rho < -lg)   { v1 =  l_t * gx; v2 =  l_t * gy; }
        else if (rho >  lg)   { v1 = -l_t * gx; v2 = -l_t * gy; }
        else if (grad > EPSf) { float s = -rho / grad; v1 = s * gx; v2 = s * gy; }
        else                  { v1 = 0.f; v2 = 0.f; }

        O1.f[k] = U1.f[k] + v1 + ts * (dx1 + dy1);
        O2.f[k] = U2.f[k] + v2 + ts * (dx2 + dy2);
    }
    st4(u1 + idx, O1.v);
    st4(u2 + idx, O2.v);
}

// ============================================================================
// Host: one quarter-pipeline on a given stream.
// ============================================================================
static void run_quarter(cudaStream_t s, int off,
                        const float* x, const float* y,
                        const float* t, const float* l, const float* a,
                        float* u1, float* u2)
{
    const int threads = 256;
    const int blocks  = (NVQ + threads - 1) / threads;
    k_init<<<blocks, threads, 0, s>>>(x, y, t, l, u1, u2, off);
    k_update_p<true><<<blocks, threads, 0, s>>>(t, a, u1, u2, off);
    for (int it = 0; it < 9; ++it) {
        k_update_u<<<blocks, threads, 0, s>>>(t, l, u1, u2, off);
        if (it < 8)
            k_update_p<false><<<blocks, threads, 0, s>>>(t, a, u1, u2, off);
    }
}

// ============================================================================
// Launch: two concurrent quarter-pipelines (fork/join capture pattern).
// Stream A: q0 then q2; stream B: q1 then q3. Active WS = 2 x 28MB = 56MB,
// same L2-resident footprint as R14's halves, but ramps/tails overlap.
// ============================================================================
extern "C" void kernel_launch(void* const* d_in, const int* in_sizes, int n_in,
                              void* d_out, int out_size)
{
    const float* x = (const float*)d_in[0];
    const float* y = (const float*)d_in[1];
    const float* t = (const float*)d_in[8];
    const float* l = (const float*)d_in[9];
    const float* a = (const float*)d_in[10];

    float* u1 = (float*)d_out;
    float* u2 = u1 + NPIX;

    static cudaStream_t s1 = 0;
    static cudaEvent_t  eF = 0, eJ = 0;
    static bool tried = false;
    if (!tried) {
        tried = true;
        if (cudaStreamCreateWithFlags(&s1, cudaStreamNonBlocking) != cudaSuccess) s1 = 0;
        if (s1) {
            if (cudaEventCreateWithFlags(&eF, cudaEventDisableTiming) != cudaSuccess ||
                cudaEventCreateWithFlags(&eJ, cudaEventDisableTiming) != cudaSuccess) {
                s1 = 0;   // fall back to single-stream (still correct)
            }
        }
    }

    if (s1) {
        // fork
        cudaEventRecord(eF, 0);
        cudaStreamWaitEvent(s1, eF, 0);
        // stream 0: quarters 0, 2 ; stream s1: quarters 1, 3
        run_quarter(0,  0 * QPIX, x, y, t, l, a, u1, u2);
        run_quarter(s1, 1 * QPIX, x, y, t, l, a, u1, u2);
        run_quarter(0,  2 * QPIX, x, y, t, l, a, u1, u2);
        run_quarter(s1, 3 * QPIX, x, y, t, l, a, u1, u2);
        // join
        cudaEventRecord(eJ, s1);
        cudaStreamWaitEvent(0, eJ, 0);
    } else {
        for (int q = 0; q < 4; ++q)
            run_quarter(0, q * QPIX, x, y, t, l, a, u1, u2);
    }
}